// round 1
// baseline (speedup 1.0000x reference)
#include <cuda_runtime.h>
#include <float.h>

#define NUM_SEG   8192
#define DCOLS     32
#define MAX_ROWS  352           // > expected max segment length (~310); fallback path covers more
#define NTHREADS  256
#define NWARPS    (NTHREADS / 32)
#define EPS       1e-10f

// Scratch (no allocations allowed): segment start offsets, fully rewritten every launch.
__device__ int g_seg_start[NUM_SEG + 1];

// ---------------------------------------------------------------------------
// Kernel 1: find segment boundaries from the sorted batch array.
// Handles both int64 and int32 on-disk layouts: values < 8192, so for int64
// every odd 32-bit word is 0; for int32 the word at [N-1] is the (nonzero) max id.
// ---------------------------------------------------------------------------
__global__ void seg_bounds_kernel(const int* __restrict__ w, int N) {
    int i = blockIdx.x * blockDim.x + threadIdx.x;
    if (i >= N) return;
    const bool is64 = (w[N - 1] == 0);   // hi-word of some int64 element -> 0; int32 last id > 0

    int b    = is64 ? w[2 * i]       : w[i];
    int prev = (i == 0) ? -1 : (is64 ? w[2 * i - 2] : w[i - 1]);

    for (int k = prev + 1; k <= b; ++k) g_seg_start[k] = i;
    if (i == N - 1) {
        for (int k = b + 1; k <= NUM_SEG; ++k) g_seg_start[k] = N;
    }
}

// ---------------------------------------------------------------------------
// Kernel 2: one CTA per segment. Rows are contiguous [start, end).
// Thread t owns column group g = t&7 (columns 4g..4g+3) -> float4 lanes.
// Pass 1: global -> smem tile, column max.
// Pass 2: smem -> exp(x-m), column sum, store e back to tile.
// Pass 3: e * 1/(sum+eps) -> global out.
// ---------------------------------------------------------------------------
__global__ __launch_bounds__(NTHREADS) void seg_softmax_kernel(
    const float* __restrict__ input, float* __restrict__ out) {

    __shared__ float4 tile[MAX_ROWS * 8];   // 45056 B
    __shared__ float4 red[NWARPS][8];       // per-warp, per-group partials
    __shared__ float4 fin_m[8];             // final per-column max (8 groups x 4 cols)
    __shared__ float4 fin_inv[8];           // final per-column 1/(sum+eps)

    const int seg   = blockIdx.x;
    const int start = g_seg_start[seg];
    const int end   = g_seg_start[seg + 1];
    const int len   = end - start;
    if (len <= 0) return;

    const int tid  = threadIdx.x;
    const int lane = tid & 31;
    const int warp = tid >> 5;
    const int g    = tid & 7;              // column group (stride 256 keeps it fixed per thread)

    const float4* inp  = reinterpret_cast<const float4*>(input) + (size_t)start * 8;
    float4*       outp = reinterpret_cast<float4*>(out)         + (size_t)start * 8;
    const int  nvec  = len * 8;            // float4's in this segment
    const bool small = (len <= MAX_ROWS);

    // ---- Pass 1: load + stage + column max --------------------------------
    float m0 = -FLT_MAX, m1 = -FLT_MAX, m2 = -FLT_MAX, m3 = -FLT_MAX;
    for (int i = tid; i < nvec; i += NTHREADS) {
        float4 v = inp[i];
        if (small) tile[i] = v;
        m0 = fmaxf(m0, v.x); m1 = fmaxf(m1, v.y);
        m2 = fmaxf(m2, v.z); m3 = fmaxf(m3, v.w);
    }
    // combine lanes sharing a column group: {l, l^8, l^16, l^24}
    #pragma unroll
    for (int off = 8; off < 32; off <<= 1) {
        m0 = fmaxf(m0, __shfl_xor_sync(0xffffffffu, m0, off));
        m1 = fmaxf(m1, __shfl_xor_sync(0xffffffffu, m1, off));
        m2 = fmaxf(m2, __shfl_xor_sync(0xffffffffu, m2, off));
        m3 = fmaxf(m3, __shfl_xor_sync(0xffffffffu, m3, off));
    }
    if (lane < 8) red[warp][lane] = make_float4(m0, m1, m2, m3);
    __syncthreads();
    if (tid < 8) {
        float4 a = red[0][tid];
        #pragma unroll
        for (int w = 1; w < NWARPS; ++w) {
            float4 b = red[w][tid];
            a.x = fmaxf(a.x, b.x); a.y = fmaxf(a.y, b.y);
            a.z = fmaxf(a.z, b.z); a.w = fmaxf(a.w, b.w);
        }
        fin_m[tid] = a;
    }
    __syncthreads();
    const float4 mv = fin_m[g];

    // ---- Pass 2: exp + column sum (store e back into tile) ----------------
    float s0 = 0.f, s1 = 0.f, s2 = 0.f, s3 = 0.f;
    for (int i = tid; i < nvec; i += NTHREADS) {
        float4 v = small ? tile[i] : inp[i];
        float e0 = __expf(v.x - mv.x);
        float e1 = __expf(v.y - mv.y);
        float e2 = __expf(v.z - mv.z);
        float e3 = __expf(v.w - mv.w);
        s0 += e0; s1 += e1; s2 += e2; s3 += e3;
        if (small) tile[i] = make_float4(e0, e1, e2, e3);
    }
    #pragma unroll
    for (int off = 8; off < 32; off <<= 1) {
        s0 += __shfl_xor_sync(0xffffffffu, s0, off);
        s1 += __shfl_xor_sync(0xffffffffu, s1, off);
        s2 += __shfl_xor_sync(0xffffffffu, s2, off);
        s3 += __shfl_xor_sync(0xffffffffu, s3, off);
    }
    __syncthreads();   // all reads of red (max phase) done before reuse
    if (lane < 8) red[warp][lane] = make_float4(s0, s1, s2, s3);
    __syncthreads();
    if (tid < 8) {
        float4 a = red[0][tid];
        #pragma unroll
        for (int w = 1; w < NWARPS; ++w) {
            float4 b = red[w][tid];
            a.x += b.x; a.y += b.y; a.z += b.z; a.w += b.w;
        }
        float4 inv;
        inv.x = 1.0f / (a.x + EPS);
        inv.y = 1.0f / (a.y + EPS);
        inv.z = 1.0f / (a.z + EPS);
        inv.w = 1.0f / (a.w + EPS);
        fin_inv[tid] = inv;
    }
    __syncthreads();
    const float4 iv = fin_inv[g];

    // ---- Pass 3: scale + write --------------------------------------------
    for (int i = tid; i < nvec; i += NTHREADS) {
        float4 e;
        if (small) {
            e = tile[i];
        } else {
            float4 v = inp[i];
            e.x = __expf(v.x - mv.x);
            e.y = __expf(v.y - mv.y);
            e.z = __expf(v.z - mv.z);
            e.w = __expf(v.w - mv.w);
        }
        e.x *= iv.x; e.y *= iv.y; e.z *= iv.z; e.w *= iv.w;
        outp[i] = e;
    }
}

// ---------------------------------------------------------------------------
extern "C" void kernel_launch(void* const* d_in, const int* in_sizes, int n_in,
                              void* d_out, int out_size) {
    const int* batch_words = (const int*)d_in[0];   // int64 or int32 layout, detected on device
    const float* x         = (const float*)d_in[1];
    float* out             = (float*)d_out;
    const int N = in_sizes[0];

    seg_bounds_kernel<<<(N + 255) / 256, 256>>>(batch_words, N);
    seg_softmax_kernel<<<NUM_SEG, NTHREADS>>>(x, out);
}